// round 1
// baseline (speedup 1.0000x reference)
#include <cuda_runtime.h>
#include <cuda_bf16.h>

#define NMAX 100000
#define DD 64

// ---------------- scratch (no allocations allowed) ----------------
__device__ float g_deg[NMAX];
__device__ float g_dis[NMAX];
__device__ float g_bufA[(size_t)NMAX * DD];
__device__ float g_bufB[(size_t)NMAX * DD];
__device__ float g_bufC[(size_t)NMAX * DD];

// ---------------- degree / normalization ----------------
__global__ void deg_kernel(const int* __restrict__ dst, int E, float* __restrict__ deg) {
    int i = blockIdx.x * blockDim.x + threadIdx.x;
    if (i < E) atomicAdd(&deg[dst[i]], 1.0f);
}

__global__ void dis_kernel(const float* __restrict__ deg, float* __restrict__ dis, int n) {
    int i = blockIdx.x * blockDim.x + threadIdx.x;
    if (i < n) dis[i] = rsqrtf(deg[i] + 1.0f);
}

// ---------------- GEMM: out = act(X @ W [+ b]) ----------------
// X: [n,64], W: [64,64] row-major (out = sum_k X[r,k]*W[k,c])
template <bool RELU>
__global__ void gemm_kernel(const float* __restrict__ X, const float* __restrict__ W,
                            const float* __restrict__ bias, float* __restrict__ out, int n) {
    __shared__ float Ws[64 * 64];
    __shared__ float Xs[4][64];
    int tid = threadIdx.x;  // 256 threads
    for (int i = tid; i < 4096; i += 256) Ws[i] = W[i];
    __syncthreads();
    int col = tid & 63;
    int r   = tid >> 6;  // 0..3
    float bv = bias ? bias[col] : 0.0f;
    for (int row0 = blockIdx.x * 4; row0 < n; row0 += gridDim.x * 4) {
        int row = row0 + r;
        if (row < n) Xs[r][col] = X[(size_t)row * 64 + col];
        __syncthreads();
        if (row < n) {
            float acc = bv;
#pragma unroll
            for (int k = 0; k < 64; k++) acc = fmaf(Xs[r][k], Ws[k * 64 + col], acc);
            out[(size_t)row * 64 + col] = RELU ? fmaxf(acc, 0.0f) : acc;
        }
        __syncthreads();
    }
}

// ---------------- SAGE combine: out = act(mean @ Wl + bl + H @ Wr + H) ----------------
template <bool RELU>
__global__ void sage_combine_kernel(const float* __restrict__ summ, const float* __restrict__ H,
                                    const float* __restrict__ deg,
                                    const float* __restrict__ Wl, const float* __restrict__ bl,
                                    const float* __restrict__ Wr,
                                    float* __restrict__ out, int n) {
    __shared__ float Wls[64 * 64];
    __shared__ float Wrs[64 * 64];
    __shared__ float Ms[4][64];
    __shared__ float Hs[4][64];
    int tid = threadIdx.x;
    for (int i = tid; i < 4096; i += 256) { Wls[i] = Wl[i]; Wrs[i] = Wr[i]; }
    __syncthreads();
    int col = tid & 63;
    int r   = tid >> 6;
    float bv = bl[col];
    for (int row0 = blockIdx.x * 4; row0 < n; row0 += gridDim.x * 4) {
        int row = row0 + r;
        if (row < n) {
            float dinv = 1.0f / fmaxf(deg[row], 1.0f);
            Ms[r][col] = summ[(size_t)row * 64 + col] * dinv;
            Hs[r][col] = H[(size_t)row * 64 + col];
        }
        __syncthreads();
        if (row < n) {
            float acc = bv + Hs[r][col];  // residual
#pragma unroll
            for (int k = 0; k < 64; k++) {
                acc = fmaf(Ms[r][k], Wls[k * 64 + col], acc);
                acc = fmaf(Hs[r][k], Wrs[k * 64 + col], acc);
            }
            out[(size_t)row * 64 + col] = RELU ? fmaxf(acc, 0.0f) : acc;
        }
        __syncthreads();
    }
}

// ---------------- GCN scatter: agg[dst] += xw[src] * dis[src]*dis[dst] ----------------
__global__ void scatter_gcn_kernel(const int* __restrict__ src, const int* __restrict__ dst,
                                   const float* __restrict__ xw, const float* __restrict__ dis,
                                   float* __restrict__ agg, int E) {
    int i = blockIdx.x * blockDim.x + threadIdx.x;
    int total = E * 16;
    if (i >= total) return;
    int e = i >> 4;
    int q = i & 15;
    int s = src[e], d = dst[e];
    float nrm = dis[s] * dis[d];
    float4 v = *(const float4*)(xw + (size_t)s * 64 + q * 4);
    v.x *= nrm; v.y *= nrm; v.z *= nrm; v.w *= nrm;
    atomicAdd((float4*)(agg + (size_t)d * 64 + q * 4), v);
}

// ---------------- plain scatter: sum[dst] += h[src] ----------------
__global__ void scatter_plain_kernel(const int* __restrict__ src, const int* __restrict__ dst,
                                     const float* __restrict__ h, float* __restrict__ summ, int E) {
    int i = blockIdx.x * blockDim.x + threadIdx.x;
    int total = E * 16;
    if (i >= total) return;
    int e = i >> 4;
    int q = i & 15;
    int s = src[e], d = dst[e];
    float4 v = *(const float4*)(h + (size_t)s * 64 + q * 4);
    atomicAdd((float4*)(summ + (size_t)d * 64 + q * 4), v);
}

// ---------------- GCN finish: out = act(agg + xw*dis^2 + b) ----------------
template <bool RELU>
__global__ void gcn_finish_kernel(const float* __restrict__ agg, const float* __restrict__ xw,
                                  const float* __restrict__ dis, const float* __restrict__ b,
                                  float* __restrict__ out, int n) {
    int i = blockIdx.x * blockDim.x + threadIdx.x;
    int total = n * 16;
    if (i >= total) return;
    int row = i >> 4;
    int q = i & 15;
    float d2 = dis[row];
    d2 *= d2;
    float4 a  = ((const float4*)agg)[i];
    float4 xv = ((const float4*)xw)[i];
    float4 bb = ((const float4*)b)[q];
    float4 o;
    o.x = a.x + xv.x * d2 + bb.x;
    o.y = a.y + xv.y * d2 + bb.y;
    o.z = a.z + xv.z * d2 + bb.z;
    o.w = a.w + xv.w * d2 + bb.w;
    if (RELU) {
        o.x = fmaxf(o.x, 0.0f); o.y = fmaxf(o.y, 0.0f);
        o.z = fmaxf(o.z, 0.0f); o.w = fmaxf(o.w, 0.0f);
    }
    ((float4*)out)[i] = o;
}

// ---------------- launch ----------------
extern "C" void kernel_launch(void* const* d_in, const int* in_sizes, int n_in,
                              void* d_out, int out_size) {
    const float* x      = (const float*)d_in[0];
    const int*   ei     = (const int*)d_in[1];
    const float* gcn1_w = (const float*)d_in[2];
    const float* gcn1_b = (const float*)d_in[3];
    const float* s1lw   = (const float*)d_in[4];
    const float* s1lb   = (const float*)d_in[5];
    const float* s1rw   = (const float*)d_in[6];
    const float* s2lw   = (const float*)d_in[7];
    const float* s2lb   = (const float*)d_in[8];
    const float* s2rw   = (const float*)d_in[9];
    const float* linw   = (const float*)d_in[10];
    const float* linb   = (const float*)d_in[11];
    const float* gcn2_w = (const float*)d_in[12];
    const float* gcn2_b = (const float*)d_in[13];

    int n = in_sizes[0] / 64;
    int E = in_sizes[1] / 2;
    const int* src = ei;
    const int* dst = ei + E;

    float *deg, *dis, *A, *B, *C;
    cudaGetSymbolAddress((void**)&deg, g_deg);
    cudaGetSymbolAddress((void**)&dis, g_dis);
    cudaGetSymbolAddress((void**)&A, g_bufA);
    cudaGetSymbolAddress((void**)&B, g_bufB);
    cudaGetSymbolAddress((void**)&C, g_bufC);

    const size_t FEAT_BYTES = (size_t)n * 64 * sizeof(float);
    const int GEMM_GRID = 592;            // ~4 blocks/SM, grid-stride over rows
    const int SC_GRID   = (E * 16 + 255) / 256;
    const int EW_GRID   = (n * 16 + 255) / 256;

    // degrees + symmetric norm
    cudaMemsetAsync(deg, 0, n * sizeof(float));
    deg_kernel<<<(E + 255) / 256, 256>>>(dst, E, deg);
    dis_kernel<<<(n + 255) / 256, 256>>>(deg, dis, n);

    // ---- layer 0: GCN1 + relu ----
    gemm_kernel<false><<<GEMM_GRID, 256>>>(x, gcn1_w, nullptr, A, n);   // xw
    cudaMemsetAsync(B, 0, FEAT_BYTES);
    scatter_gcn_kernel<<<SC_GRID, 256>>>(src, dst, A, dis, B, E);
    gcn_finish_kernel<true><<<EW_GRID, 256>>>(B, A, dis, gcn1_b, C, n); // h -> C

    // ---- layer 1: SAGE1 + residual + relu ----
    cudaMemsetAsync(B, 0, FEAT_BYTES);
    scatter_plain_kernel<<<SC_GRID, 256>>>(src, dst, C, B, E);
    sage_combine_kernel<true><<<GEMM_GRID, 256>>>(B, C, deg, s1lw, s1lb, s1rw, A, n); // h -> A

    // ---- layer 2: SAGE2 + residual (no relu) ----
    cudaMemsetAsync(B, 0, FEAT_BYTES);
    scatter_plain_kernel<<<SC_GRID, 256>>>(src, dst, A, B, E);
    sage_combine_kernel<false><<<GEMM_GRID, 256>>>(B, A, deg, s2lw, s2lb, s2rw, C, n); // h -> C

    // ---- lin + relu ----
    gemm_kernel<true><<<GEMM_GRID, 256>>>(C, linw, linb, A, n);         // h -> A

    // ---- layer 3: GCN2 (no activation) ----
    gemm_kernel<false><<<GEMM_GRID, 256>>>(A, gcn2_w, nullptr, C, n);   // xw
    cudaMemsetAsync(B, 0, FEAT_BYTES);
    scatter_gcn_kernel<<<SC_GRID, 256>>>(src, dst, C, dis, B, E);
    gcn_finish_kernel<false><<<EW_GRID, 256>>>(B, C, dis, gcn2_b, (float*)d_out, n);
}

// round 2
// speedup vs baseline: 2.6403x; 2.6403x over previous
#include <cuda_runtime.h>
#include <cuda_bf16.h>

#define NMAX 100000
#define EMAX 1250000
#define DD 64

// ---------------- scratch ----------------
__device__ int   g_degi[NMAX];
__device__ float g_degf[NMAX];
__device__ float g_dis[NMAX];
__device__ int   g_rowptr[NMAX + 1];
__device__ int   g_cursor[NMAX];
__device__ int   g_csr[EMAX];
__device__ int   g_blocksums[512];
__device__ float g_bufA[(size_t)NMAX * DD];
__device__ float g_bufB[(size_t)NMAX * DD];
__device__ float g_bufC[(size_t)NMAX * DD];

// ---------------- degree ----------------
__global__ void deg_count_kernel(const int* __restrict__ dst, int E, int* __restrict__ degi) {
    int i = blockIdx.x * blockDim.x + threadIdx.x;
    if (i < E) atomicAdd(&degi[dst[i]], 1);
}

__global__ void dis_kernel(const int* __restrict__ degi, float* __restrict__ degf,
                           float* __restrict__ dis, int n) {
    int i = blockIdx.x * blockDim.x + threadIdx.x;
    if (i < n) {
        float d = (float)degi[i];
        degf[i] = d;
        dis[i] = rsqrtf(d + 1.0f);
    }
}

// ---------------- exclusive scan (3 kernels, n <= 512*512) ----------------
__global__ void scan1_kernel(const int* __restrict__ cnt, int* __restrict__ out,
                             int* __restrict__ bsums, int n) {
    __shared__ int s[512];
    int i = blockIdx.x * 512 + threadIdx.x;
    int v = (i < n) ? cnt[i] : 0;
    s[threadIdx.x] = v;
    __syncthreads();
    for (int off = 1; off < 512; off <<= 1) {
        int t = (threadIdx.x >= off) ? s[threadIdx.x - off] : 0;
        __syncthreads();
        s[threadIdx.x] += t;
        __syncthreads();
    }
    if (i < n + 1 && i < gridDim.x * 512) { /* bound below */ }
    if (i < n) out[i] = s[threadIdx.x] - v;   // exclusive within block
    if (threadIdx.x == 511) bsums[blockIdx.x] = s[511];
}

__global__ void scan2_kernel(int* __restrict__ bsums, int nb) {
    __shared__ int s[512];
    int v = (threadIdx.x < nb) ? bsums[threadIdx.x] : 0;
    s[threadIdx.x] = v;
    __syncthreads();
    for (int off = 1; off < 512; off <<= 1) {
        int t = (threadIdx.x >= off) ? s[threadIdx.x - off] : 0;
        __syncthreads();
        s[threadIdx.x] += t;
        __syncthreads();
    }
    if (threadIdx.x < nb) bsums[threadIdx.x] = s[threadIdx.x] - v;  // exclusive
}

__global__ void scan3_kernel(int* __restrict__ rowptr, const int* __restrict__ bsums,
                             int* __restrict__ cursor, int n, int E) {
    int i = blockIdx.x * 512 + threadIdx.x;
    if (i < n) {
        int v = rowptr[i] + bsums[blockIdx.x];
        rowptr[i] = v;
        cursor[i] = v;
    }
    if (i == n) rowptr[n] = E;
}

__global__ void fill_csr_kernel(const int* __restrict__ src, const int* __restrict__ dst,
                                int* __restrict__ cursor, int* __restrict__ csr, int E) {
    int i = blockIdx.x * blockDim.x + threadIdx.x;
    if (i < E) {
        int pos = atomicAdd(&cursor[dst[i]], 1);
        csr[pos] = src[i];
    }
}

// ---------------- gather: per-node aggregation, float4 lanes ----------------
// GCN=true : out = relu?(sum_e xw[s]*dis[s]*dis[d] + xw[d]*dis[d]^2 + bias)
// GCN=false: out = sum_e h[s]   (raw sum; SAGE combine divides by deg)
template <bool GCN, bool RELU>
__global__ void gather_kernel(const int* __restrict__ rowptr, const int* __restrict__ csr,
                              const float* __restrict__ xw, const float* __restrict__ dis,
                              const float* __restrict__ bias, float* __restrict__ out, int n) {
    int node = blockIdx.x * 16 + (threadIdx.x >> 4);
    int q = threadIdx.x & 15;
    if (node >= n) return;
    int beg = rowptr[node], end = rowptr[node + 1];
    float4 acc = make_float4(0.f, 0.f, 0.f, 0.f);
    const float4* xwv = (const float4*)xw;
    int e = beg;
    for (; e + 1 < end; e += 2) {
        int s0 = csr[e], s1 = csr[e + 1];
        float4 v0 = xwv[(size_t)s0 * 16 + q];
        float4 v1 = xwv[(size_t)s1 * 16 + q];
        if (GCN) {
            float w0 = dis[s0], w1 = dis[s1];
            acc.x += v0.x * w0 + v1.x * w1;
            acc.y += v0.y * w0 + v1.y * w1;
            acc.z += v0.z * w0 + v1.z * w1;
            acc.w += v0.w * w0 + v1.w * w1;
        } else {
            acc.x += v0.x + v1.x; acc.y += v0.y + v1.y;
            acc.z += v0.z + v1.z; acc.w += v0.w + v1.w;
        }
    }
    if (e < end) {
        int s = csr[e];
        float4 v = xwv[(size_t)s * 16 + q];
        float w = GCN ? dis[s] : 1.0f;
        acc.x += v.x * w; acc.y += v.y * w; acc.z += v.z * w; acc.w += v.w * w;
    }
    if (GCN) {
        float dd = dis[node];
        float d2 = dd * dd;
        float4 xv = xwv[(size_t)node * 16 + q];
        float4 bb = ((const float4*)bias)[q];
        acc.x = acc.x * dd + xv.x * d2 + bb.x;
        acc.y = acc.y * dd + xv.y * d2 + bb.y;
        acc.z = acc.z * dd + xv.z * d2 + bb.z;
        acc.w = acc.w * dd + xv.w * d2 + bb.w;
        if (RELU) {
            acc.x = fmaxf(acc.x, 0.f); acc.y = fmaxf(acc.y, 0.f);
            acc.z = fmaxf(acc.z, 0.f); acc.w = fmaxf(acc.w, 0.f);
        }
    }
    ((float4*)out)[(size_t)node * 16 + q] = acc;
}

// ---------------- register-tiled GEMM: out = act(X @ W [+ b]) ----------------
// 64x64 tile per block, 256 threads, 4x4 micro-tile per thread.
template <bool RELU, bool BIAS>
__global__ void __launch_bounds__(256) gemm64_kernel(
    const float* __restrict__ X, const float* __restrict__ W,
    const float* __restrict__ bias, float* __restrict__ out, int n) {
    __shared__ float Ws[64][64];
    __shared__ float Xs[64][65];
    int tid = threadIdx.x;
    int row0 = blockIdx.x * 64;
    // load W [64,64]
    {
        const float4* Wv = (const float4*)W;
        float4* Wsv = (float4*)&Ws[0][0];
        for (int i = tid; i < 1024; i += 256) Wsv[i] = Wv[i];
    }
    // load X tile [64 rows][64 cols]
    for (int j = tid; j < 1024; j += 256) {
        int r = j >> 4, c4 = (j & 15) * 4;
        float4 v = (row0 + r < n) ? ((const float4*)X)[(size_t)(row0 + r) * 16 + (j & 15)]
                                  : make_float4(0.f, 0.f, 0.f, 0.f);
        Xs[r][c4] = v.x; Xs[r][c4 + 1] = v.y; Xs[r][c4 + 2] = v.z; Xs[r][c4 + 3] = v.w;
    }
    __syncthreads();

    int rq = (tid >> 4) * 4;   // 4 rows
    int cq = (tid & 15) * 4;   // 4 cols
    float acc[4][4];
#pragma unroll
    for (int i = 0; i < 4; i++)
#pragma unroll
        for (int j = 0; j < 4; j++) acc[i][j] = 0.f;

#pragma unroll 8
    for (int k = 0; k < 64; k++) {
        float4 w = *(const float4*)&Ws[k][cq];
        float xr0 = Xs[rq + 0][k], xr1 = Xs[rq + 1][k];
        float xr2 = Xs[rq + 2][k], xr3 = Xs[rq + 3][k];
        acc[0][0] = fmaf(xr0, w.x, acc[0][0]); acc[0][1] = fmaf(xr0, w.y, acc[0][1]);
        acc[0][2] = fmaf(xr0, w.z, acc[0][2]); acc[0][3] = fmaf(xr0, w.w, acc[0][3]);
        acc[1][0] = fmaf(xr1, w.x, acc[1][0]); acc[1][1] = fmaf(xr1, w.y, acc[1][1]);
        acc[1][2] = fmaf(xr1, w.z, acc[1][2]); acc[1][3] = fmaf(xr1, w.w, acc[1][3]);
        acc[2][0] = fmaf(xr2, w.x, acc[2][0]); acc[2][1] = fmaf(xr2, w.y, acc[2][1]);
        acc[2][2] = fmaf(xr2, w.z, acc[2][2]); acc[2][3] = fmaf(xr2, w.w, acc[2][3]);
        acc[3][0] = fmaf(xr3, w.x, acc[3][0]); acc[3][1] = fmaf(xr3, w.y, acc[3][1]);
        acc[3][2] = fmaf(xr3, w.z, acc[3][2]); acc[3][3] = fmaf(xr3, w.w, acc[3][3]);
    }

    float4 bb = BIAS ? ((const float4*)bias)[cq >> 2] : make_float4(0.f, 0.f, 0.f, 0.f);
#pragma unroll
    for (int i = 0; i < 4; i++) {
        int row = row0 + rq + i;
        if (row < n) {
            float4 o;
            o.x = acc[i][0] + bb.x; o.y = acc[i][1] + bb.y;
            o.z = acc[i][2] + bb.z; o.w = acc[i][3] + bb.w;
            if (RELU) {
                o.x = fmaxf(o.x, 0.f); o.y = fmaxf(o.y, 0.f);
                o.z = fmaxf(o.z, 0.f); o.w = fmaxf(o.w, 0.f);
            }
            ((float4*)out)[(size_t)row * 16 + (cq >> 2)] = o;
        }
    }
}

// ---------------- SAGE combine: out = act((sum/deg) @ Wl + bl + H @ Wr + H) ----------------
template <bool RELU>
__global__ void __launch_bounds__(256) sage64_kernel(
    const float* __restrict__ summ, const float* __restrict__ H,
    const float* __restrict__ degf,
    const float* __restrict__ Wl, const float* __restrict__ bl,
    const float* __restrict__ Wr, float* __restrict__ out, int n) {
    __shared__ float Wls[64][64];
    __shared__ float Wrs[64][64];
    __shared__ float Ms[64][65];
    __shared__ float Hs[64][65];
    int tid = threadIdx.x;
    int row0 = blockIdx.x * 64;
    {
        const float4* Wlv = (const float4*)Wl;
        const float4* Wrv = (const float4*)Wr;
        float4* Wlsv = (float4*)&Wls[0][0];
        float4* Wrsv = (float4*)&Wrs[0][0];
        for (int i = tid; i < 1024; i += 256) { Wlsv[i] = Wlv[i]; Wrsv[i] = Wrv[i]; }
    }
    for (int j = tid; j < 1024; j += 256) {
        int r = j >> 4, c4 = (j & 15) * 4;
        float4 m = make_float4(0.f, 0.f, 0.f, 0.f), h = m;
        if (row0 + r < n) {
            float dinv = 1.0f / fmaxf(degf[row0 + r], 1.0f);
            m = ((const float4*)summ)[(size_t)(row0 + r) * 16 + (j & 15)];
            m.x *= dinv; m.y *= dinv; m.z *= dinv; m.w *= dinv;
            h = ((const float4*)H)[(size_t)(row0 + r) * 16 + (j & 15)];
        }
        Ms[r][c4] = m.x; Ms[r][c4 + 1] = m.y; Ms[r][c4 + 2] = m.z; Ms[r][c4 + 3] = m.w;
        Hs[r][c4] = h.x; Hs[r][c4 + 1] = h.y; Hs[r][c4 + 2] = h.z; Hs[r][c4 + 3] = h.w;
    }
    __syncthreads();

    int rq = (tid >> 4) * 4;
    int cq = (tid & 15) * 4;
    float acc[4][4];
#pragma unroll
    for (int i = 0; i < 4; i++)
#pragma unroll
        for (int j = 0; j < 4; j++) acc[i][j] = 0.f;

#pragma unroll 4
    for (int k = 0; k < 64; k++) {
        float4 wl = *(const float4*)&Wls[k][cq];
        float4 wr = *(const float4*)&Wrs[k][cq];
#pragma unroll
        for (int i = 0; i < 4; i++) {
            float m = Ms[rq + i][k];
            float h = Hs[rq + i][k];
            acc[i][0] = fmaf(m, wl.x, fmaf(h, wr.x, acc[i][0]));
            acc[i][1] = fmaf(m, wl.y, fmaf(h, wr.y, acc[i][1]));
            acc[i][2] = fmaf(m, wl.z, fmaf(h, wr.z, acc[i][2]));
            acc[i][3] = fmaf(m, wl.w, fmaf(h, wr.w, acc[i][3]));
        }
    }

    float4 bb = ((const float4*)bl)[cq >> 2];
#pragma unroll
    for (int i = 0; i < 4; i++) {
        int row = row0 + rq + i;
        if (row < n) {
            float4 o;  // + residual H
            o.x = acc[i][0] + bb.x + Hs[rq + i][cq + 0];
            o.y = acc[i][1] + bb.y + Hs[rq + i][cq + 1];
            o.z = acc[i][2] + bb.z + Hs[rq + i][cq + 2];
            o.w = acc[i][3] + bb.w + Hs[rq + i][cq + 3];
            if (RELU) {
                o.x = fmaxf(o.x, 0.f); o.y = fmaxf(o.y, 0.f);
                o.z = fmaxf(o.z, 0.f); o.w = fmaxf(o.w, 0.f);
            }
            ((float4*)out)[(size_t)row * 16 + (cq >> 2)] = o;
        }
    }
}

// ---------------- launch ----------------
extern "C" void kernel_launch(void* const* d_in, const int* in_sizes, int n_in,
                              void* d_out, int out_size) {
    const float* x      = (const float*)d_in[0];
    const int*   ei     = (const int*)d_in[1];
    const float* gcn1_w = (const float*)d_in[2];
    const float* gcn1_b = (const float*)d_in[3];
    const float* s1lw   = (const float*)d_in[4];
    const float* s1lb   = (const float*)d_in[5];
    const float* s1rw   = (const float*)d_in[6];
    const float* s2lw   = (const float*)d_in[7];
    const float* s2lb   = (const float*)d_in[8];
    const float* s2rw   = (const float*)d_in[9];
    const float* linw   = (const float*)d_in[10];
    const float* linb   = (const float*)d_in[11];
    const float* gcn2_w = (const float*)d_in[12];
    const float* gcn2_b = (const float*)d_in[13];

    int n = in_sizes[0] / 64;
    int E = in_sizes[1] / 2;
    const int* src = ei;
    const int* dst = ei + E;

    int *degi, *rowptr, *cursor, *csr, *bsums;
    float *degf, *dis, *A, *B, *C;
    cudaGetSymbolAddress((void**)&degi, g_degi);
    cudaGetSymbolAddress((void**)&degf, g_degf);
    cudaGetSymbolAddress((void**)&dis, g_dis);
    cudaGetSymbolAddress((void**)&rowptr, g_rowptr);
    cudaGetSymbolAddress((void**)&cursor, g_cursor);
    cudaGetSymbolAddress((void**)&csr, g_csr);
    cudaGetSymbolAddress((void**)&bsums, g_blocksums);
    cudaGetSymbolAddress((void**)&A, g_bufA);
    cudaGetSymbolAddress((void**)&B, g_bufB);
    cudaGetSymbolAddress((void**)&C, g_bufC);

    const int GEMM_GRID = (n + 63) / 64;
    const int GATH_GRID = (n + 15) / 16;
    const int NB = (n + 511) / 512;

    // degrees + CSR build
    cudaMemsetAsync(degi, 0, n * sizeof(int));
    deg_count_kernel<<<(E + 255) / 256, 256>>>(dst, E, degi);
    dis_kernel<<<(n + 255) / 256, 256>>>(degi, degf, dis, n);
    scan1_kernel<<<NB, 512>>>(degi, rowptr, bsums, n);
    scan2_kernel<<<1, 512>>>(bsums, NB);
    scan3_kernel<<<(n + 512) / 512, 512>>>(rowptr, bsums, cursor, n, E);
    fill_csr_kernel<<<(E + 255) / 256, 256>>>(src, dst, cursor, csr, E);

    // ---- layer 0: GCN1 + relu ----
    gemm64_kernel<false, false><<<GEMM_GRID, 256>>>(x, gcn1_w, nullptr, A, n);   // xw
    gather_kernel<true, true><<<GATH_GRID, 256>>>(rowptr, csr, A, dis, gcn1_b, C, n);  // h

    // ---- layer 1: SAGE1 + residual + relu ----
    gather_kernel<false, false><<<GATH_GRID, 256>>>(rowptr, csr, C, dis, nullptr, B, n);
    sage64_kernel<true><<<GEMM_GRID, 256>>>(B, C, degf, s1lw, s1lb, s1rw, A, n);  // h -> A

    // ---- layer 2: SAGE2 + residual ----
    gather_kernel<false, false><<<GATH_GRID, 256>>>(rowptr, csr, A, dis, nullptr, B, n);
    sage64_kernel<false><<<GEMM_GRID, 256>>>(B, A, degf, s2lw, s2lb, s2rw, C, n); // h -> C

    // ---- lin + relu ----
    gemm64_kernel<true, true><<<GEMM_GRID, 256>>>(C, linw, linb, A, n);           // h -> A

    // ---- layer 3: GCN2 ----
    gemm64_kernel<false, false><<<GEMM_GRID, 256>>>(A, gcn2_w, nullptr, C, n);    // xw
    gather_kernel<true, false><<<GATH_GRID, 256>>>(rowptr, csr, C, dis, gcn2_b, (float*)d_out, n);
}